// round 1
// baseline (speedup 1.0000x reference)
#include <cuda_runtime.h>
#include <cuda_bf16.h>
#include <math.h>

// Problem constants
#define U_CNT 512
#define P_CNT 1024
#define D_DIM 128
#define H_DIM 256
#define E_CNT 98304
#define N_NODES 1536
#define CSR_CAP (E_CNT + N_NODES)

// ---------------- scratch (device globals; no allocation allowed) -------------
__device__ float g_xA[N_NODES * H_DIM];   // node features ping
__device__ float g_xB[N_NODES * H_DIM];   // node features pong
__device__ float g_h [N_NODES * H_DIM];   // pre-aggregation h = x @ W
__device__ int   g_deg[N_NODES];
__device__ float g_dis[N_NODES];
__device__ int   g_ptr[N_NODES + 1];
__device__ int   g_cnt[N_NODES];
__device__ int   g_src[CSR_CAP];
__device__ float g_uf[U_CNT * D_DIM];
__device__ float g_pf[P_CNT * D_DIM];
__device__ float g_Au[U_CNT * H_DIM];
__device__ float g_Bp[P_CNT * H_DIM];

// ---------------- graph preprocessing ----------------------------------------
__global__ void init_kernel() {
    int i = blockIdx.x * blockDim.x + threadIdx.x;
    if (i < N_NODES) { g_deg[i] = 1; g_cnt[i] = 0; }  // 1 = self loop
}

__global__ void count_kernel(const int* __restrict__ edge, int E) {
    int e = blockIdx.x * blockDim.x + threadIdx.x;
    if (e < E) atomicAdd(&g_deg[edge[E + e]], 1);
}

// single block: dis = rsqrt(deg); exclusive prefix sum deg -> ptr
__global__ void scan_kernel() {
    __shared__ int buf[2][N_NODES];
    int t = threadIdx.x;                 // 1024 threads
    for (int i = t; i < N_NODES; i += 1024) {
        int dg = g_deg[i];
        buf[0][i] = dg;
        g_dis[i] = rsqrtf((float)dg);
    }
    __syncthreads();
    int pin = 0;
    for (int off = 1; off < N_NODES; off <<= 1) {
        for (int i = t; i < N_NODES; i += 1024) {
            int v = buf[pin][i];
            if (i >= off) v += buf[pin][i - off];
            buf[1 - pin][i] = v;
        }
        pin ^= 1;
        __syncthreads();
    }
    for (int i = t; i < N_NODES; i += 1024) g_ptr[i + 1] = buf[pin][i];
    if (t == 0) g_ptr[0] = 0;
}

__global__ void fill_kernel(const int* __restrict__ edge, int E) {
    int idx = blockIdx.x * blockDim.x + threadIdx.x;
    int total = E + N_NODES;
    if (idx >= total) return;
    int s, d;
    if (idx < E) { s = edge[idx]; d = edge[E + idx]; }
    else         { s = d = idx - E; }                  // self loop
    int pos = g_ptr[d] + atomicAdd(&g_cnt[d], 1);
    g_src[pos] = s;
}

// ---------------- embedding gather -------------------------------------------
__global__ void build_x0(const int* __restrict__ uid, const int* __restrict__ pid,
                         const float* __restrict__ ue, const float* __restrict__ pe) {
    int i = blockIdx.x;           // node
    int d = threadIdx.x;          // feature (128)
    float v;
    if (i < U_CNT) v = ue[uid[i] * D_DIM + d];
    else           v = pe[pid[i - U_CNT] * D_DIM + d];
    g_xA[i * D_DIM + d] = v;
}

// ---------------- generic fp32 GEMM: C[M,N] = X[M,K] @ W[K,N] (+bias) --------
// grid: (N/64, M/64), block: 256 threads, 4x4 per thread, BK=16
__global__ void gemm_kernel(const float* __restrict__ X, const float* __restrict__ W,
                            const float* __restrict__ bias, float* __restrict__ C,
                            int M, int N, int K) {
    __shared__ float Xs[16][65];
    __shared__ float Ws[16][64];
    int tid = threadIdx.x;
    int tx = tid & 15, ty = tid >> 4;
    int bm = blockIdx.y * 64, bn = blockIdx.x * 64;
    float acc[4][4] = {};
    for (int k0 = 0; k0 < K; k0 += 16) {
        {   // X tile: 64 rows x 16 k, transposed into Xs[k][row]
            int kk = tid & 15, r = tid >> 4;
            #pragma unroll
            for (int rr = 0; rr < 4; rr++)
                Xs[kk][r + rr * 16] = X[(bm + r + rr * 16) * K + k0 + kk];
        }
        {   // W tile: 16 k x 64 cols
            int c = tid & 63, kr = tid >> 6;
            #pragma unroll
            for (int rr = 0; rr < 4; rr++)
                Ws[kr + rr * 4][c] = W[(k0 + kr + rr * 4) * N + bn + c];
        }
        __syncthreads();
        #pragma unroll
        for (int k = 0; k < 16; k++) {
            float ra[4], rb[4];
            #pragma unroll
            for (int i = 0; i < 4; i++) ra[i] = Xs[k][ty * 4 + i];
            #pragma unroll
            for (int j = 0; j < 4; j++) rb[j] = Ws[k][tx * 4 + j];
            #pragma unroll
            for (int i = 0; i < 4; i++)
                #pragma unroll
                for (int j = 0; j < 4; j++)
                    acc[i][j] += ra[i] * rb[j];
        }
        __syncthreads();
    }
    #pragma unroll
    for (int i = 0; i < 4; i++) {
        int row = bm + ty * 4 + i;
        #pragma unroll
        for (int j = 0; j < 4; j++) {
            int col = bn + tx * 4 + j;
            float v = acc[i][j];
            if (bias) v += bias[col];
            C[row * N + col] = v;
        }
    }
}

// ---------------- GCN aggregation: out[d] = relu(sum_e norm*h[src] + b) ------
// grid: N_NODES blocks, block: 256 threads (one per feature)
__global__ void aggregate_kernel(const float* __restrict__ h,
                                 const float* __restrict__ bias,
                                 float* __restrict__ out) {
    __shared__ int   s_src[128];
    __shared__ float s_w[128];
    int dst = blockIdx.x;
    int f = threadIdx.x;
    float dd = g_dis[dst];
    int s0 = g_ptr[dst], s1 = g_ptr[dst + 1];
    float acc = 0.f;
    for (int base = s0; base < s1; base += 128) {
        int n = min(128, s1 - base);
        if (f < n) {
            int sc = g_src[base + f];
            s_src[f] = sc;
            s_w[f] = g_dis[sc] * dd;
        }
        __syncthreads();
        #pragma unroll 4
        for (int i = 0; i < n; i++)
            acc += h[s_src[i] * H_DIM + f] * s_w[i];
        __syncthreads();
    }
    out[dst * H_DIM + f] = fmaxf(acc + bias[f], 0.f);
}

// ---------------- pairwise predictor -----------------------------------------
// pred[u,p] = sigmoid(bq2 + sum_j relu(A[u,j]+B[p,j]) * w2[j])
// grid: (P/64, U/64), block 256, 4x4 pairs/thread, j chunked by 32
__global__ void pred_kernel(const float* __restrict__ A, const float* __restrict__ B,
                            const float* __restrict__ w2, const float* __restrict__ b2,
                            float* __restrict__ out) {
    __shared__ float As[64][33];
    __shared__ float Bs[64][33];
    __shared__ float ws[32];
    int tid = threadIdx.x;
    int tx = tid & 15, ty = tid >> 4;
    int u0 = blockIdx.y * 64, p0 = blockIdx.x * 64;
    float acc[4][4] = {};
    for (int j0 = 0; j0 < H_DIM; j0 += 32) {
        int c = tid & 31, r0 = tid >> 5;       // 8 rows per thread
        #pragma unroll
        for (int rr = 0; rr < 8; rr++) {
            As[r0 + rr * 8][c] = A[(u0 + r0 + rr * 8) * H_DIM + j0 + c];
            Bs[r0 + rr * 8][c] = B[(p0 + r0 + rr * 8) * H_DIM + j0 + c];
        }
        if (tid < 32) ws[tid] = w2[j0 + tid];
        __syncthreads();
        #pragma unroll
        for (int j = 0; j < 32; j++) {
            float wv = ws[j];
            float av[4], bv[4];
            #pragma unroll
            for (int i = 0; i < 4; i++) av[i] = As[ty * 4 + i][j];
            #pragma unroll
            for (int jj = 0; jj < 4; jj++) bv[jj] = Bs[tx * 4 + jj][j];
            #pragma unroll
            for (int i = 0; i < 4; i++)
                #pragma unroll
                for (int jj = 0; jj < 4; jj++)
                    acc[i][jj] += fmaxf(av[i] + bv[jj], 0.f) * wv;
        }
        __syncthreads();
    }
    float bb = b2[0];
    #pragma unroll
    for (int i = 0; i < 4; i++) {
        int u = u0 + ty * 4 + i;
        #pragma unroll
        for (int jj = 0; jj < 4; jj++) {
            int p = p0 + tx * 4 + jj;
            float z = acc[i][jj] + bb;
            out[u * P_CNT + p] = 1.f / (1.f + __expf(-z));
        }
    }
}

// ---------------- driver ------------------------------------------------------
extern "C" void kernel_launch(void* const* d_in, const int* in_sizes, int n_in,
                              void* d_out, int out_size) {
    const int*   uid  = (const int*)  d_in[0];
    const int*   pid  = (const int*)  d_in[1];
    const int*   edge = (const int*)  d_in[2];
    // d_in[3] = user_paper_interactions (unused by the reference math)
    const float* ue   = (const float*)d_in[4];
    const float* pe   = (const float*)d_in[5];
    const float* W0   = (const float*)d_in[6];  const float* b0 = (const float*)d_in[7];
    const float* W1   = (const float*)d_in[8];  const float* b1 = (const float*)d_in[9];
    const float* W2   = (const float*)d_in[10]; const float* b2 = (const float*)d_in[11];
    const float* Wu   = (const float*)d_in[12]; const float* bu = (const float*)d_in[13];
    const float* Wp   = (const float*)d_in[14]; const float* bp = (const float*)d_in[15];
    const float* Wq1  = (const float*)d_in[16]; const float* bq1= (const float*)d_in[17];
    const float* Wq2  = (const float*)d_in[18]; const float* bq2= (const float*)d_in[19];
    float* out = (float*)d_out;
    int E = in_sizes[2] / 2;

    // resolve device-global scratch addresses (query only; no allocation)
    float *xA, *xB, *h, *uf, *pf, *Au, *Bp;
    cudaGetSymbolAddress((void**)&xA, g_xA);
    cudaGetSymbolAddress((void**)&xB, g_xB);
    cudaGetSymbolAddress((void**)&h,  g_h);
    cudaGetSymbolAddress((void**)&uf, g_uf);
    cudaGetSymbolAddress((void**)&pf, g_pf);
    cudaGetSymbolAddress((void**)&Au, g_Au);
    cudaGetSymbolAddress((void**)&Bp, g_Bp);

    // 1. graph preprocessing (CSR with self loops + symmetric norm)
    init_kernel<<<(N_NODES + 255) / 256, 256>>>();
    build_x0<<<N_NODES, D_DIM>>>(uid, pid, ue, pe);        // x0 -> g_xA [N,128]
    count_kernel<<<(E + 255) / 256, 256>>>(edge, E);
    scan_kernel<<<1, 1024>>>();
    fill_kernel<<<(E + N_NODES + 255) / 256, 256>>>(edge, E);

    // 2. three GCN layers: h = x @ W ; x' = relu(segsum(norm*h) + b)
    gemm_kernel<<<dim3(H_DIM / 64, N_NODES / 64), 256>>>(xA, W0, nullptr, h, N_NODES, H_DIM, D_DIM);
    aggregate_kernel<<<N_NODES, H_DIM>>>(h, b0, xB);

    gemm_kernel<<<dim3(H_DIM / 64, N_NODES / 64), 256>>>(xB, W1, nullptr, h, N_NODES, H_DIM, H_DIM);
    aggregate_kernel<<<N_NODES, H_DIM>>>(h, b1, xA);

    gemm_kernel<<<dim3(H_DIM / 64, N_NODES / 64), 256>>>(xA, W2, nullptr, h, N_NODES, H_DIM, H_DIM);
    aggregate_kernel<<<N_NODES, H_DIM>>>(h, b2, xB);

    // 3. output projections (no relu)
    gemm_kernel<<<dim3(D_DIM / 64, U_CNT / 64), 256>>>(xB, Wu, bu, uf, U_CNT, D_DIM, H_DIM);
    gemm_kernel<<<dim3(D_DIM / 64, P_CNT / 64), 256>>>(xB + U_CNT * H_DIM, Wp, bp, pf, P_CNT, D_DIM, H_DIM);

    // 4. predictor split: A = uf @ Wq1[:128] + bq1 ; B = pf @ Wq1[128:]
    gemm_kernel<<<dim3(H_DIM / 64, U_CNT / 64), 256>>>(uf, Wq1, bq1, Au, U_CNT, H_DIM, D_DIM);
    gemm_kernel<<<dim3(H_DIM / 64, P_CNT / 64), 256>>>(pf, Wq1 + D_DIM * H_DIM, nullptr, Bp, P_CNT, H_DIM, D_DIM);

    // 5. pairwise sigmoid(relu(A[u]+B[p]) . w2 + b)
    pred_kernel<<<dim3(P_CNT / 64, U_CNT / 64), 256>>>(Au, Bp, Wq2, bq2, out);
}

// round 2
// speedup vs baseline: 1.2814x; 1.2814x over previous
#include <cuda_runtime.h>
#include <cuda_bf16.h>
#include <math.h>

// Problem constants
#define U_CNT 512
#define P_CNT 1024
#define D_DIM 128
#define H_DIM 256
#define E_CNT 98304
#define N_NODES 1536
#define CSR_CAP (E_CNT + N_NODES)

typedef unsigned long long u64;

// ---------------- packed f32x2 helpers (sm_100+) ------------------------------
__device__ __forceinline__ u64 pack2(float lo, float hi) {
    u64 r; asm("mov.b64 %0,{%1,%2};" : "=l"(r) : "f"(lo), "f"(hi)); return r;
}
__device__ __forceinline__ void unpack2(u64 v, float& lo, float& hi) {
    asm("mov.b64 {%0,%1},%2;" : "=f"(lo), "=f"(hi) : "l"(v));
}
__device__ __forceinline__ u64 add2(u64 a, u64 b) {
    u64 r; asm("add.rn.f32x2 %0,%1,%2;" : "=l"(r) : "l"(a), "l"(b)); return r;
}
__device__ __forceinline__ void fma2(u64& d, u64 a, u64 b) {
    asm("fma.rn.f32x2 %0,%1,%2,%0;" : "+l"(d) : "l"(a), "l"(b));
}
__device__ __forceinline__ u64 abs2(u64 a) {
    u64 r; asm("and.b64 %0,%1,0x7FFFFFFF7FFFFFFF;" : "=l"(r) : "l"(a)); return r;
}

// ---------------- scratch (device globals; no allocation allowed) -------------
__device__ float g_xA[N_NODES * H_DIM];
__device__ float g_xB[N_NODES * H_DIM];
__device__ float g_h [N_NODES * H_DIM];
__device__ int   g_deg[N_NODES];          // zero-init; scan resets to 0 each call
__device__ float g_dis[N_NODES];
__device__ int   g_ptr[N_NODES + 1];
__device__ int   g_cnt[N_NODES];          // zero-init; scan resets to 0 each call
__device__ int   g_src[CSR_CAP];
__device__ float g_uf[U_CNT * D_DIM];
__device__ float g_pf[P_CNT * D_DIM];
__device__ float g_Au[U_CNT * H_DIM];
__device__ float g_Bp[P_CNT * H_DIM];

// ---------------- x0 gather + degree count (fused) ----------------------------
__global__ void build_x0(const int* __restrict__ uid, const int* __restrict__ pid,
                         const float* __restrict__ ue, const float* __restrict__ pe,
                         const int* __restrict__ edge) {
    int i = blockIdx.x;           // node (1536)
    int d = threadIdx.x;          // feature (128)
    float v;
    if (i < U_CNT) v = ue[uid[i] * D_DIM + d];
    else           v = pe[pid[i - U_CNT] * D_DIM + d];
    g_xA[i * D_DIM + d] = v;
    int e = i * 128 + d;          // 196608 threads >= E
    if (e < E_CNT) atomicAdd(&g_deg[edge[E_CNT + e]], 1);
}

// single warp: deg+1 (self loop), rsqrt, exclusive scan -> ptr, reset deg/cnt
__global__ void scan_kernel() {
    int lane = threadIdx.x;                 // 32 threads
    const int PER = N_NODES / 32;           // 48
    int base = lane * PER;
    int v[PER]; int s = 0;
    #pragma unroll
    for (int i = 0; i < PER; i++) v[i] = g_deg[base + i] + 1;
    #pragma unroll
    for (int i = 0; i < PER; i++) {
        g_dis[base + i] = rsqrtf((float)v[i]);
        s += v[i];
        g_deg[base + i] = 0;
        g_cnt[base + i] = 0;
    }
    int incl = s;
    #pragma unroll
    for (int off = 1; off < 32; off <<= 1) {
        int u = __shfl_up_sync(0xffffffffu, incl, off);
        if (lane >= off) incl += u;
    }
    int run = incl - s;                     // exclusive prefix
    if (lane == 0) g_ptr[0] = 0;
    #pragma unroll
    for (int i = 0; i < PER; i++) { run += v[i]; g_ptr[base + i + 1] = run; }
}

__global__ void fill_kernel(const int* __restrict__ edge, int E) {
    int idx = blockIdx.x * blockDim.x + threadIdx.x;
    int total = E + N_NODES;
    if (idx >= total) return;
    int s, d;
    if (idx < E) { s = edge[idx]; d = edge[E + idx]; }
    else         { s = d = idx - E; }                  // self loop
    int pos = g_ptr[d] + atomicAdd(&g_cnt[d], 1);
    g_src[pos] = s;
}

// ---------------- GCN aggregation (pure segsum, aggregate-first) --------------
// out[dst] = sum_{src in nb(dst)} dis[src]*dis[dst] * h[src]
template<int F>
__global__ void aggregate_kernel(const float* __restrict__ h, float* __restrict__ out) {
    __shared__ int   s_src[128];
    __shared__ float s_w[128];
    int dst = blockIdx.x, t = threadIdx.x;   // 128 threads
    float dd = g_dis[dst];
    int s0 = g_ptr[dst], s1 = g_ptr[dst + 1];
    float ax = 0.f, ay = 0.f;
    for (int base = s0; base < s1; base += 128) {
        int n = min(128, s1 - base);
        if (t < n) { int sc = g_src[base + t]; s_src[t] = sc; s_w[t] = g_dis[sc] * dd; }
        __syncthreads();
        if (F == 256) {
            #pragma unroll 4
            for (int i = 0; i < n; i++) {
                float2 v = *(const float2*)(h + s_src[i] * F + 2 * t);
                ax += v.x * s_w[i]; ay += v.y * s_w[i];
            }
        } else {
            #pragma unroll 4
            for (int i = 0; i < n; i++)
                ax += h[s_src[i] * F + t] * s_w[i];
        }
        __syncthreads();
    }
    if (F == 256) { float2 o = make_float2(ax, ay); *(float2*)(out + dst * F + 2 * t) = o; }
    else out[dst * F + t] = ax;
}

// ---------------- fp32 GEMM core with packed FFMA2 ----------------------------
// C[bm:bm+64, bn:bn+64] = X @ W (+bias, +relu). K,N multiples of 16/64.
__device__ __forceinline__ void gemm_core(
    float (*Xs)[65], float (*Ws)[64],
    const float* __restrict__ X, const float* __restrict__ W,
    const float* __restrict__ bias, float* __restrict__ C,
    int N, int K, int bm, int bn, int relu)
{
    int tid = threadIdx.x;
    int tx = tid & 15, ty = tid >> 4;
    u64 acc[4][2] = {};
    for (int k0 = 0; k0 < K; k0 += 16) {
        {   // X tile: 64 rows x 16 k, transposed
            int kk = tid & 15, r = tid >> 4;
            #pragma unroll
            for (int rr = 0; rr < 4; rr++)
                Xs[kk][r + rr * 16] = X[(bm + r + rr * 16) * K + k0 + kk];
        }
        {   // W tile: 16 k x 64 cols
            int c = tid & 63, kr = tid >> 6;
            #pragma unroll
            for (int rr = 0; rr < 4; rr++)
                Ws[kr + rr * 4][c] = W[(k0 + kr + rr * 4) * N + bn + c];
        }
        __syncthreads();
        #pragma unroll
        for (int k = 0; k < 16; k++) {
            float4 rb = *(const float4*)&Ws[k][tx * 4];
            u64 rb01 = pack2(rb.x, rb.y), rb23 = pack2(rb.z, rb.w);
            #pragma unroll
            for (int i = 0; i < 4; i++) {
                float a = Xs[k][ty * 4 + i];
                u64 a2 = pack2(a, a);
                fma2(acc[i][0], a2, rb01);
                fma2(acc[i][1], a2, rb23);
            }
        }
        __syncthreads();
    }
    #pragma unroll
    for (int i = 0; i < 4; i++) {
        int row = bm + ty * 4 + i;
        #pragma unroll
        for (int jp = 0; jp < 2; jp++) {
            float lo, hi; unpack2(acc[i][jp], lo, hi);
            int col = bn + tx * 4 + jp * 2;
            if (bias) { lo += bias[col]; hi += bias[col + 1]; }
            if (relu) { lo = fmaxf(lo, 0.f); hi = fmaxf(hi, 0.f); }
            float2 o = make_float2(lo, hi);
            *(float2*)&C[row * N + col] = o;
        }
    }
}

__global__ void gemm_kernel(const float* __restrict__ X, const float* __restrict__ W,
                            const float* __restrict__ bias, float* __restrict__ C,
                            int N, int K, int relu) {
    __shared__ __align__(16) float Xs[16][65];
    __shared__ __align__(16) float Ws[16][64];
    gemm_core(Xs, Ws, X, W, bias, C, N, K, blockIdx.y * 64, blockIdx.x * 64, relu);
}

// two independent GEMMs with same N,K fused into one launch (split on blockIdx.y)
__global__ void gemm_dual_kernel(const float* __restrict__ Xa, const float* __restrict__ Wa,
                                 const float* __restrict__ ba, float* __restrict__ Ca, int cut,
                                 const float* __restrict__ Xb, const float* __restrict__ Wb,
                                 const float* __restrict__ bb_, float* __restrict__ Cb,
                                 int N, int K, int relu) {
    __shared__ __align__(16) float Xs[16][65];
    __shared__ __align__(16) float Ws[16][64];
    if ((int)blockIdx.y < cut)
        gemm_core(Xs, Ws, Xa, Wa, ba, Ca, N, K, blockIdx.y * 64, blockIdx.x * 64, relu);
    else
        gemm_core(Xs, Ws, Xb, Wb, bb_, Cb, N, K, (blockIdx.y - cut) * 64, blockIdx.x * 64, relu);
}

// ---------------- pairwise predictor ------------------------------------------
// pred[u,p] = sigmoid(bq2 + sum_j relu(A[u,j]+B[p,j]) * w2[j])
// relu(s)*w = (w/2)*s + (w/2)*|s|  -> packed f32x2, pairs natural along j
__global__ void pred_kernel(const float* __restrict__ A, const float* __restrict__ B,
                            const float* __restrict__ w2, const float* __restrict__ bq2,
                            float* __restrict__ out) {
    __shared__ __align__(16) float As[64][34];
    __shared__ __align__(16) float Bs[64][34];
    __shared__ u64 wh2[16];
    int tid = threadIdx.x;
    int tx = tid & 15, ty = tid >> 4;
    int u0 = blockIdx.y * 64, p0 = blockIdx.x * 64;
    u64 acc[4][4] = {};
    for (int j0 = 0; j0 < H_DIM; j0 += 32) {
        int c = tid & 31, r = tid >> 5;
        #pragma unroll
        for (int rr = 0; rr < 8; rr++) {
            As[r + rr * 8][c] = A[(u0 + r + rr * 8) * H_DIM + j0 + c];
            Bs[r + rr * 8][c] = B[(p0 + r + rr * 8) * H_DIM + j0 + c];
        }
        if (tid < 16) wh2[tid] = pack2(0.5f * w2[j0 + 2 * tid], 0.5f * w2[j0 + 2 * tid + 1]);
        __syncthreads();
        #pragma unroll
        for (int jp = 0; jp < 16; jp++) {
            u64 wv = wh2[jp];
            u64 av[4], bv[4];
            #pragma unroll
            for (int i = 0; i < 4; i++)  av[i] = *(const u64*)&As[ty + 16 * i][2 * jp];
            #pragma unroll
            for (int jj = 0; jj < 4; jj++) bv[jj] = *(const u64*)&Bs[tx + 16 * jj][2 * jp];
            #pragma unroll
            for (int i = 0; i < 4; i++)
                #pragma unroll
                for (int jj = 0; jj < 4; jj++) {
                    u64 s = add2(av[i], bv[jj]);
                    u64 a = abs2(s);
                    fma2(acc[i][jj], wv, s);
                    fma2(acc[i][jj], wv, a);
                }
        }
        __syncthreads();
    }
    float bb = bq2[0];
    #pragma unroll
    for (int i = 0; i < 4; i++) {
        int u = u0 + ty + 16 * i;
        #pragma unroll
        for (int jj = 0; jj < 4; jj++) {
            int p = p0 + tx + 16 * jj;
            float lo, hi; unpack2(acc[i][jj], lo, hi);
            float z = lo + hi + bb;
            out[u * P_CNT + p] = 1.f / (1.f + __expf(-z));
        }
    }
}

// ---------------- driver ------------------------------------------------------
extern "C" void kernel_launch(void* const* d_in, const int* in_sizes, int n_in,
                              void* d_out, int out_size) {
    const int*   uid  = (const int*)  d_in[0];
    const int*   pid  = (const int*)  d_in[1];
    const int*   edge = (const int*)  d_in[2];
    // d_in[3] = user_paper_interactions (unused by the reference math)
    const float* ue   = (const float*)d_in[4];
    const float* pe   = (const float*)d_in[5];
    const float* W0   = (const float*)d_in[6];  const float* b0 = (const float*)d_in[7];
    const float* W1   = (const float*)d_in[8];  const float* b1 = (const float*)d_in[9];
    const float* W2   = (const float*)d_in[10]; const float* b2 = (const float*)d_in[11];
    const float* Wu   = (const float*)d_in[12]; const float* bu = (const float*)d_in[13];
    const float* Wp   = (const float*)d_in[14]; const float* bp = (const float*)d_in[15];
    const float* Wq1  = (const float*)d_in[16]; const float* bq1= (const float*)d_in[17];
    const float* Wq2  = (const float*)d_in[18]; const float* bq2= (const float*)d_in[19];
    float* out = (float*)d_out;

    float *xA, *xB, *h, *uf, *pf, *Au, *Bp;
    cudaGetSymbolAddress((void**)&xA, g_xA);
    cudaGetSymbolAddress((void**)&xB, g_xB);
    cudaGetSymbolAddress((void**)&h,  g_h);
    cudaGetSymbolAddress((void**)&uf, g_uf);
    cudaGetSymbolAddress((void**)&pf, g_pf);
    cudaGetSymbolAddress((void**)&Au, g_Au);
    cudaGetSymbolAddress((void**)&Bp, g_Bp);

    // 1. preprocessing: x0 gather + degree count, scan, CSR fill
    build_x0<<<N_NODES, D_DIM>>>(uid, pid, ue, pe, edge);
    scan_kernel<<<1, 32>>>();
    fill_kernel<<<(E_CNT + N_NODES + 255) / 256, 256>>>(edge, E_CNT);

    // 2. three GCN layers, aggregate-first: x' = relu(Agg(x) @ W + b)
    aggregate_kernel<128><<<N_NODES, 128>>>(xA, xB);                     // [N,128]
    gemm_kernel<<<dim3(H_DIM / 64, N_NODES / 64), 256>>>(xB, W0, b0, xA, H_DIM, D_DIM, 1);

    aggregate_kernel<256><<<N_NODES, 128>>>(xA, h);                      // [N,256]
    gemm_kernel<<<dim3(H_DIM / 64, N_NODES / 64), 256>>>(h, W1, b1, xB, H_DIM, H_DIM, 1);

    aggregate_kernel<256><<<N_NODES, 128>>>(xB, h);
    gemm_kernel<<<dim3(H_DIM / 64, N_NODES / 64), 256>>>(h, W2, b2, xA, H_DIM, H_DIM, 1);

    // 3. output projections (fused): uf = xA_u @ Wu + bu ; pf = xA_p @ Wp + bp
    gemm_dual_kernel<<<dim3(D_DIM / 64, (U_CNT + P_CNT) / 64), 256>>>(
        xA, Wu, bu, uf, U_CNT / 64,
        xA + U_CNT * H_DIM, Wp, bp, pf,
        D_DIM, H_DIM, 0);

    // 4. predictor split (fused): Au = uf @ Wq1[:128] + bq1 ; Bp = pf @ Wq1[128:]
    gemm_dual_kernel<<<dim3(H_DIM / 64, (U_CNT + P_CNT) / 64), 256>>>(
        uf, Wq1, bq1, Au, U_CNT / 64,
        pf, Wq1 + D_DIM * H_DIM, nullptr, Bp,
        H_DIM, D_DIM, 0);

    // 5. pairwise sigmoid(relu(A[u]+B[p]) . w2 + bq2)
    pred_kernel<<<dim3(P_CNT / 64, U_CNT / 64), 256>>>(Au, Bp, Wq2, bq2, out);
}